// round 16
// baseline (speedup 1.0000x reference)
#include <cuda_runtime.h>
#include <cuda_bf16.h>
#include <math.h>
#include <stdint.h>

// ---------------- problem constants ----------------
#define D_MODEL   512
#define HEADS     8
#define DH        64
#define BATCH     32
#define S_CURR    128
#define N_MASK    16
#define N_CAND    39998
#define M_GATH    (BATCH * N_MASK)   // 512
#define NROWS_KV  (BATCH * S_CURR)   // 4096

// ---------------- scratch (static device memory) ----------------
__device__ __nv_bfloat16 g_currhi[NROWS_KV * D_MODEL];
__device__ __nv_bfloat16 g_currlo[NROWS_KV * D_MODEL];
__device__ __nv_bfloat16 g_qinhi [M_GATH * D_MODEL];
__device__ __nv_bfloat16 g_qinlo [M_GATH * D_MODEL];
__device__ __nv_bfloat16 g_wkhi[D_MODEL * D_MODEL], g_wklo[D_MODEL * D_MODEL];
__device__ __nv_bfloat16 g_wvhi[D_MODEL * D_MODEL], g_wvlo[D_MODEL * D_MODEL];
__device__ __nv_bfloat16 g_wqhi[D_MODEL * D_MODEL], g_wqlo[D_MODEL * D_MODEL];
__device__ __nv_bfloat16 g_twhi[D_MODEL * D_MODEL], g_twlo[D_MODEL * D_MODEL];
__device__ __nv_bfloat16 g_embhi[(size_t)N_CAND * D_MODEL];
__device__ __nv_bfloat16 g_emblo[(size_t)N_CAND * D_MODEL];
__device__ __nv_bfloat16 g_t2ahi[M_GATH * D_MODEL], g_t2alo[M_GATH * D_MODEL];
__device__ __nv_bfloat16 g_hybhi[M_GATH * D_MODEL], g_hyblo[M_GATH * D_MODEL];
__device__ float g_K  [NROWS_KV * D_MODEL];
__device__ float g_V  [NROWS_KV * D_MODEL];
__device__ float g_Qm [M_GATH * D_MODEL];
__device__ float g_att[M_GATH * D_MODEL];
__device__ float g_hyb[M_GATH * D_MODEL];
#define NT_SCORES 313                 // ceil(40064/128)
__device__ float g_pm[M_GATH * NT_SCORES];
__device__ float g_ps[M_GATH * NT_SCORES];
__device__ float g_lse[M_GATH];

// =======================================================================
// helpers
// =======================================================================
__device__ __forceinline__ uint32_t smem_u32(const void* p) {
    uint32_t a;
    asm("{ .reg .u64 t; cvta.to.shared.u64 t, %1; cvt.u32.u64 %0, t; }"
        : "=r"(a) : "l"(p));
    return a;
}

#define LDSM4(r0, r1, r2, r3, addr) \
    asm volatile("ldmatrix.sync.aligned.m8n8.x4.shared.b16 {%0,%1,%2,%3}, [%4];" \
                 : "=r"(r0), "=r"(r1), "=r"(r2), "=r"(r3) : "r"(addr))

#define MMA16816(d, a, b) \
    asm volatile("mma.sync.aligned.m16n8k16.row.col.f32.bf16.bf16.f32 " \
                 "{%0,%1,%2,%3}, {%4,%5,%6,%7}, {%8,%9}, {%0,%1,%2,%3};" \
                 : "+f"((d)[0]), "+f"((d)[1]), "+f"((d)[2]), "+f"((d)[3]) \
                 : "r"((a)[0]), "r"((a)[1]), "r"((a)[2]), "r"((a)[3]), \
                   "r"((b)[0]), "r"((b)[1]))

#define CP_ASYNC16(dst, src, sz) \
    asm volatile("cp.async.cg.shared.global [%0], [%1], 16, %2;" \
                 :: "r"(dst), "l"(src), "r"(sz))
#define CP_COMMIT() asm volatile("cp.async.commit_group;" ::: "memory")
#define CP_WAIT2()  asm volatile("cp.async.wait_group 2;" ::: "memory")

// safe logsumexp combine
__device__ __forceinline__ void lse_comb(float& m, float& s, float m2, float s2) {
    float M = fmaxf(m, m2);
    if (M == -INFINITY) { m = M; s = 0.f; return; }
    s = s * expf(m - M) + s2 * expf(m2 - M);
    m = M;
}

// split one float4 into packed bf16 hi/lo
__device__ __forceinline__ void split4(float4 v, uint2& h, uint2& l) {
    __nv_bfloat162 h01 = __floats2bfloat162_rn(v.x, v.y);
    __nv_bfloat162 h23 = __floats2bfloat162_rn(v.z, v.w);
    float lx = v.x - __bfloat162float(h01.x);
    float ly = v.y - __bfloat162float(h01.y);
    float lz = v.z - __bfloat162float(h23.x);
    float lw = v.w - __bfloat162float(h23.y);
    __nv_bfloat162 l01 = __floats2bfloat162_rn(lx, ly);
    __nv_bfloat162 l23 = __floats2bfloat162_rn(lz, lw);
    h = make_uint2(*reinterpret_cast<unsigned*>(&h01), *reinterpret_cast<unsigned*>(&h23));
    l = make_uint2(*reinterpret_cast<unsigned*>(&l01), *reinterpret_cast<unsigned*>(&l23));
}

// =======================================================================
// split kernels
// =======================================================================
__global__ void split_kernel(const float* __restrict__ src,
                             __nv_bfloat16* __restrict__ hi,
                             __nv_bfloat16* __restrict__ lo, int n4) {
    int i = blockIdx.x * blockDim.x + threadIdx.x;
    if (i >= n4) return;
    uint2 h, l;
    split4(((const float4*)src)[i], h, l);
    ((uint2*)hi)[i] = h;
    ((uint2*)lo)[i] = l;
}

// fused split of the four 512x512 weight matrices (one launch)
__global__ void split4w_kernel(const float* __restrict__ w0, const float* __restrict__ w1,
                               const float* __restrict__ w2, const float* __restrict__ w3,
                               __nv_bfloat16* __restrict__ h0, __nv_bfloat16* __restrict__ l0,
                               __nv_bfloat16* __restrict__ h1, __nv_bfloat16* __restrict__ l1,
                               __nv_bfloat16* __restrict__ h2, __nv_bfloat16* __restrict__ l2,
                               __nv_bfloat16* __restrict__ h3, __nv_bfloat16* __restrict__ l3) {
    const int W4 = D_MODEL * D_MODEL / 4;
    int i = blockIdx.x * blockDim.x + threadIdx.x;
    int which = i / W4;
    int j = i - which * W4;
    const float* src; __nv_bfloat16 *hi, *lo;
    if      (which == 0) { src = w0; hi = h0; lo = l0; }
    else if (which == 1) { src = w1; hi = h1; lo = l1; }
    else if (which == 2) { src = w2; hi = h2; lo = l2; }
    else                 { src = w3; hi = h3; lo = l3; }
    uint2 h, l;
    split4(((const float4*)src)[j], h, l);
    ((uint2*)hi)[j] = h;
    ((uint2*)lo)[j] = l;
}

__global__ void tanh_split_kernel(const float* __restrict__ src,
                                  __nv_bfloat16* __restrict__ hi,
                                  __nv_bfloat16* __restrict__ lo, int n4) {
    int i = blockIdx.x * blockDim.x + threadIdx.x;
    if (i >= n4) return;
    float4 v = ((const float4*)src)[i];
    v.x = tanhf(v.x); v.y = tanhf(v.y); v.z = tanhf(v.z); v.w = tanhf(v.w);
    uint2 h, l;
    split4(v, h, l);
    ((uint2*)hi)[i] = h;
    ((uint2*)lo)[i] = l;
}

// =======================================================================
// positional embedding + gathers (write bf16 hi/lo directly)
// =======================================================================
__device__ __forceinline__ float pe_val(int pos, int d) {
    const float c = -9.210340371976184f / (float)D_MODEL;  // -ln(10000)/512
    int i2 = d & ~1;
    float freq = expf((float)i2 * c);
    float arg = (float)pos * freq;
    return (d & 1) ? cosf(arg) : sinf(arg);
}

__global__ void build_curr_kernel(const int* __restrict__ idx,
                                  const float* __restrict__ emb) {
    int t = blockIdx.x * blockDim.x + threadIdx.x;     // one float4
    if (t >= NROWS_KV * D_MODEL / 4) return;
    int e  = t * 4;
    int d0 = e & (D_MODEL - 1);
    int row = e >> 9;
    int s  = row & (S_CURR - 1);
    int g  = idx[row];
    float4 v = *(const float4*)(emb + (size_t)g * D_MODEL + d0);
    v.x += pe_val(s, d0);     v.y += pe_val(s, d0 + 1);
    v.z += pe_val(s, d0 + 2); v.w += pe_val(s, d0 + 3);
    uint2 h, l;
    split4(v, h, l);
    ((uint2*)g_currhi)[t] = h;
    ((uint2*)g_currlo)[t] = l;
}

__global__ void build_qin_kernel(const int* __restrict__ idx,
                                 const int* __restrict__ mask_pos,
                                 const float* __restrict__ emb) {
    int t = blockIdx.x * blockDim.x + threadIdx.x;
    if (t >= M_GATH * D_MODEL / 4) return;
    int e  = t * 4;
    int d0 = e & (D_MODEL - 1);
    int r  = e >> 9;                  // b*16+i
    int b  = r >> 4;
    int s  = mask_pos[r];
    int g  = idx[b * S_CURR + s];
    float4 v = *(const float4*)(emb + (size_t)g * D_MODEL + d0);
    v.x += pe_val(s, d0);     v.y += pe_val(s, d0 + 1);
    v.z += pe_val(s, d0 + 2); v.w += pe_val(s, d0 + 3);
    uint2 h, l;
    split4(v, h, l);
    ((uint2*)g_qinhi)[t] = h;
    ((uint2*)g_qinlo)[t] = l;
}

// =======================================================================
// generic bf16 hi/lo HMMA GEMM (projections): CTA 128x128, 512 threads,
// 16 warps 4x4, warp tile 32x32, 4-stage cp.async. (round-15 kernel)
// =======================================================================
#define NCHUNK   16
#define LDTB     80
#define TILE_SZ  (128 * LDTB)        // 10240
#define OFF_AHI  0u
#define OFF_ALO  (1u * TILE_SZ)
#define OFF_BHI  (2u * TILE_SZ)
#define OFF_BLO  (3u * TILE_SZ)
#define STAGE_SZ (4u * TILE_SZ)      // 40960
#define GSMEM    (4 * 40960)         // 163840

__device__ __forceinline__ void issue_chunk(
    uint32_t stBase,
    const __nv_bfloat16* __restrict__ Ahi, const __nv_bfloat16* __restrict__ Alo,
    const __nv_bfloat16* __restrict__ Bhi, const __nv_bfloat16* __restrict__ Blo,
    int mBase, int nBase, int Nrows, int kt, int tid)
{
#pragma unroll
    for (int i = 0; i < 4; i++) {
        int idx  = tid + i * 512;     // 0..2047
        int tile = idx >> 9;
        int w    = idx & 511;
        int row  = w >> 2;
        int c16  = w & 3;
        uint32_t dst = stBase + tile * TILE_SZ + row * LDTB + c16 * 16;
        const __nv_bfloat16* base =
            (tile == 0) ? Ahi : (tile == 1) ? Alo : (tile == 2) ? Bhi : Blo;
        int gr = (tile < 2) ? (mBase + row) : (nBase + row);
        int sz = 16;
        if (tile >= 2 && gr >= Nrows) { sz = 0; gr = 0; }
        const char* src = (const char*)base + (long long)gr * 1024 + kt * 64 + c16 * 16;
        CP_ASYNC16(dst, src, sz);
    }
}

#define LOADF(s, buf) do {                                                   \
    uint32_t aT = smb + sOff + AO[s] + mW * LDTB + laneOff + KO[s];          \
    LDSM4(a2[buf][0][0], a2[buf][0][1], a2[buf][0][2], a2[buf][0][3], aT);   \
    LDSM4(a2[buf][1][0], a2[buf][1][1], a2[buf][1][2], a2[buf][1][3],       \
          aT + 16 * LDTB);                                                   \
    uint32_t bT = smb + sOff + BO[s] + nW * LDTB + laneOff + KO[s];          \
    uint32_t r0_, r1_, r2_, r3_;                                             \
    LDSM4(r0_, r1_, r2_, r3_, bT);                                           \
    b2[buf][0][0] = r0_; b2[buf][0][1] = r2_;                                \
    b2[buf][1][0] = r1_; b2[buf][1][1] = r3_;                                \
    LDSM4(r0_, r1_, r2_, r3_, bT + 16 * LDTB);                               \
    b2[buf][2][0] = r0_; b2[buf][2][1] = r2_;                                \
    b2[buf][3][0] = r1_; b2[buf][3][1] = r3_;                                \
} while (0)

__global__ __launch_bounds__(512, 1)
void gemm_bf16_kernel(const __nv_bfloat16* __restrict__ Ahi,
                      const __nv_bfloat16* __restrict__ Alo,
                      const __nv_bfloat16* __restrict__ Bhi,
                      const __nv_bfloat16* __restrict__ Blo,
                      const float* __restrict__ bias,
                      float* __restrict__ C,
                      int Nrows, int ldc)
{
    extern __shared__ char sm[];
    const uint32_t smb = smem_u32(sm);
    const int tid  = threadIdx.x;
    const int lane = tid & 31;
    const int wid  = tid >> 5;
    const int mBase = blockIdx.x * 128;
    const int nBase = blockIdx.y * 128;
    const int mW = (wid & 3) * 32;
    const int nW = (wid >> 2) * 32;
    const uint32_t laneOff = (lane & 15) * LDTB + (lane >> 4) * 16;

    float acc[2][4][4];
#pragma unroll
    for (int mf = 0; mf < 2; mf++)
#pragma unroll
        for (int nf = 0; nf < 4; nf++)
#pragma unroll
            for (int j = 0; j < 4; j++) acc[mf][nf][j] = 0.f;

#pragma unroll
    for (int c = 0; c < 3; c++) {
        issue_chunk(smb + c * STAGE_SZ, Ahi, Alo, Bhi, Blo,
                    mBase, nBase, Nrows, c, tid);
        CP_COMMIT();
    }

    const uint32_t AO[6] = {OFF_AHI, OFF_AHI, OFF_AHI, OFF_AHI, OFF_ALO, OFF_ALO};
    const uint32_t BO[6] = {OFF_BHI, OFF_BHI, OFF_BLO, OFF_BLO, OFF_BHI, OFF_BHI};
    const uint32_t KO[6] = {0, 32, 0, 32, 0, 32};

#pragma unroll 1
    for (int kt = 0; kt < NCHUNK; kt++) {
        CP_WAIT2();
        __syncthreads();
        if (kt + 3 < NCHUNK)
            issue_chunk(smb + ((kt + 3) & 3) * STAGE_SZ, Ahi, Alo, Bhi, Blo,
                        mBase, nBase, Nrows, kt + 3, tid);
        CP_COMMIT();

        const uint32_t sOff = (kt & 3) * STAGE_SZ;
        uint32_t a2[2][2][4];
        uint32_t b2[2][4][2];
        LOADF(0, 0);
#pragma unroll
        for (int s = 0; s < 6; s++) {
            const int cur = s & 1;
            if (s < 5) LOADF(s + 1, cur ^ 1);
#pragma unroll
            for (int mf = 0; mf < 2; mf++)
#pragma unroll
                for (int nf = 0; nf < 4; nf++)
                    MMA16816(acc[mf][nf], a2[cur][mf], b2[cur][nf]);
        }
    }

    const int r0l = lane >> 2;
    const int c0l = (lane & 3) * 2;
#pragma unroll
    for (int mf = 0; mf < 2; mf++) {
#pragma unroll
        for (int nf = 0; nf < 4; nf++) {
            int row = mBase + mW + mf * 16 + r0l;
            int col = nBase + nW + nf * 8 + c0l;
            float* cp0 = C + (long long)row * ldc;
            float* cp1 = C + (long long)(row + 8) * ldc;
            if (col + 1 < Nrows) {
                float b0 = bias ? bias[col] : 0.f;
                float b1 = bias ? bias[col + 1] : 0.f;
                *(float2*)(cp0 + col) = make_float2(acc[mf][nf][0] + b0,
                                                    acc[mf][nf][1] + b1);
                *(float2*)(cp1 + col) = make_float2(acc[mf][nf][2] + b0,
                                                    acc[mf][nf][3] + b1);
            } else if (col < Nrows) {
                float b0 = bias ? bias[col] : 0.f;
                cp0[col] = acc[mf][nf][0] + b0;
                cp1[col] = acc[mf][nf][2] + b0;
            }
        }
    }
}

// =======================================================================
// scores GEMM: CTA tile 256x128, 256 threads, 8 warps 4x2, warp tile
// 64x64 (128 B smem-read per MMA — half of the 32x32 design), 3-stage
// cp.async. Fused per-tile logsumexp partials.
// =======================================================================
#define S_LDTB   80
#define SA_TILE  (256 * S_LDTB)      // 20480
#define SB_TILE  (128 * S_LDTB)      // 10240
#define SOA_HI   0u
#define SOA_LO   20480u
#define SOB_HI   40960u
#define SOB_LO   51200u
#define S_STAGE  61440u
#define SSMEM    (3 * 61440)         // 184320

__device__ __forceinline__ void issue_chunk_s(
    uint32_t stBase,
    const __nv_bfloat16* __restrict__ Ahi, const __nv_bfloat16* __restrict__ Alo,
    const __nv_bfloat16* __restrict__ Bhi, const __nv_bfloat16* __restrict__ Blo,
    int mBase, int nBase, int Nrows, int kt, int tid)
{
    // A hi: 1024 16B ops (256 rows x 4)
#pragma unroll
    for (int i = 0; i < 4; i++) {
        int idx = tid + i * 256;
        int row = idx >> 2, c16 = idx & 3;
        uint32_t dst = stBase + SOA_HI + row * S_LDTB + c16 * 16;
        const char* src = (const char*)Ahi + (long long)(mBase + row) * 1024 + kt * 64 + c16 * 16;
        CP_ASYNC16(dst, src, 16);
    }
#pragma unroll
    for (int i = 0; i < 4; i++) {
        int idx = tid + i * 256;
        int row = idx >> 2, c16 = idx & 3;
        uint32_t dst = stBase + SOA_LO + row * S_LDTB + c16 * 16;
        const char* src = (const char*)Alo + (long long)(mBase + row) * 1024 + kt * 64 + c16 * 16;
        CP_ASYNC16(dst, src, 16);
    }
    // B hi/lo: 512 ops each (128 rows x 4)
#pragma unroll
    for (int i = 0; i < 2; i++) {
        int idx = tid + i * 256;
        int row = idx >> 2, c16 = idx & 3;
        int gr = nBase + row;
        int sz = (gr < Nrows) ? 16 : 0;
        if (!sz) gr = 0;
        uint32_t dst = stBase + SOB_HI + row * S_LDTB + c16 * 16;
        const char* src = (const char*)Bhi + (long long)gr * 1024 + kt * 64 + c16 * 16;
        CP_ASYNC16(dst, src, sz);
    }
#pragma unroll
    for (int i = 0; i < 2; i++) {
        int idx = tid + i * 256;
        int row = idx >> 2, c16 = idx & 3;
        int gr = nBase + row;
        int sz = (gr < Nrows) ? 16 : 0;
        if (!sz) gr = 0;
        uint32_t dst = stBase + SOB_LO + row * S_LDTB + c16 * 16;
        const char* src = (const char*)Blo + (long long)gr * 1024 + kt * 64 + c16 * 16;
        CP_ASYNC16(dst, src, sz);
    }
}

__global__ __launch_bounds__(256, 1)
void gemm_scores_kernel(const __nv_bfloat16* __restrict__ Ahi,
                        const __nv_bfloat16* __restrict__ Alo,
                        const __nv_bfloat16* __restrict__ Bhi,
                        const __nv_bfloat16* __restrict__ Blo,
                        float* __restrict__ C,
                        int Nrows, int ldc,
                        float* __restrict__ pm, float* __restrict__ ps)
{
    extern __shared__ char sm[];
    const uint32_t smb = smem_u32(sm);
    const int tid  = threadIdx.x;
    const int lane = tid & 31;
    const int wid  = tid >> 5;
    const int mBase = blockIdx.x * 256;
    const int nBase = blockIdx.y * 128;
    const int mW = (wid & 3) * 64;      // 4 warps in m
    const int nW = (wid >> 2) * 64;     // 2 warps in n
    const uint32_t laneOff = (lane & 15) * S_LDTB + (lane >> 4) * 16;

    float acc[4][8][4];
#pragma unroll
    for (int mf = 0; mf < 4; mf++)
#pragma unroll
        for (int nf = 0; nf < 8; nf++)
#pragma unroll
            for (int j = 0; j < 4; j++) acc[mf][nf][j] = 0.f;

#pragma unroll
    for (int c = 0; c < 3; c++) {
        issue_chunk_s(smb + c * S_STAGE, Ahi, Alo, Bhi, Blo,
                      mBase, nBase, Nrows, c, tid);
        CP_COMMIT();
    }

    const uint32_t AO[6] = {SOA_HI, SOA_HI, SOA_HI, SOA_HI, SOA_LO, SOA_LO};
    const uint32_t BO[6] = {SOB_HI, SOB_HI, SOB_LO, SOB_LO, SOB_HI, SOB_HI};
    const uint32_t KO[6] = {0, 32, 0, 32, 0, 32};

    int stage = 0;
#pragma unroll 1
    for (int kt = 0; kt < NCHUNK; kt++) {
        CP_WAIT2();
        __syncthreads();
        const uint32_t sOff = stage * S_STAGE;
#pragma unroll
        for (int s = 0; s < 6; s++) {
            uint32_t a[4][4];
            uint32_t b[8][2];
            uint32_t aT = smb + sOff + AO[s] + mW * S_LDTB + laneOff + KO[s];
#pragma unroll
            for (int q = 0; q < 4; q++)
                LDSM4(a[q][0], a[q][1], a[q][2], a[q][3], aT + q * 16 * S_LDTB);
            uint32_t bT = smb + sOff + BO[s] + nW * S_LDTB + laneOff + KO[s];
#pragma unroll
            for (int q = 0; q < 4; q++) {
                uint32_t r0, r1, r2, r3;
                LDSM4(r0, r1, r2, r3, bT + q * 16 * S_LDTB);
                b[2 * q][0] = r0;      b[2 * q][1] = r2;
                b[2 * q + 1][0] = r1;  b[2 * q + 1][1] = r3;
            }
#pragma unroll
            for (int mf = 0; mf < 4; mf++)
#pragma unroll
                for (int nf = 0; nf < 8; nf++)
                    MMA16816(acc[mf][nf], a[mf], b[nf]);
        }
        if (kt + 3 < NCHUNK) {
            __syncthreads();           // all warps done reading this stage
            issue_chunk_s(smb + stage * S_STAGE, Ahi, Alo, Bhi, Blo,
                          mBase, nBase, Nrows, kt + 3, tid);
        }
        CP_COMMIT();                   // empty group keeps wait accounting uniform
        stage = (stage == 2) ? 0 : stage + 1;
    }

    // ---------------- C write ----------------
    const int r0l = lane >> 2;
    const int c0l = (lane & 3) * 2;
#pragma unroll
    for (int mf = 0; mf < 4; mf++) {
#pragma unroll
        for (int nf = 0; nf < 8; nf++) {
            int row = mBase + mW + mf * 16 + r0l;
            int col = nBase + nW + nf * 8 + c0l;
            float* cp0 = C + (long long)row * ldc;
            float* cp1 = C + (long long)(row + 8) * ldc;
            if (col + 1 < Nrows) {
                *(float2*)(cp0 + col) = make_float2(acc[mf][nf][0], acc[mf][nf][1]);
                *(float2*)(cp1 + col) = make_float2(acc[mf][nf][2], acc[mf][nf][3]);
            } else if (col < Nrows) {
                cp0[col] = acc[mf][nf][0];
                cp1[col] = acc[mf][nf][2];
            }
        }
    }

    // ---------------- fused logsumexp partials ----------------
    __syncthreads();                    // stage smem free for reuse
    float2* partSm = (float2*)sm;       // 2 x 256 float2 = 4 KB
    const int wm = wid & 3;
    const int wn = wid >> 2;
#pragma unroll
    for (int mf = 0; mf < 4; mf++) {
#pragma unroll
        for (int h = 0; h < 2; h++) {
            float m = -INFINITY;
#pragma unroll
            for (int nf = 0; nf < 8; nf++)
#pragma unroll
                for (int j = 0; j < 2; j++) {
                    int col = nBase + nW + nf * 8 + c0l + j;
                    if (col < Nrows) m = fmaxf(m, acc[mf][nf][h * 2 + j]);
                }
            float s = 0.f;
#pragma unroll
            for (int nf = 0; nf < 8; nf++)
#pragma unroll
                for (int j = 0; j < 2; j++) {
                    int col = nBase + nW + nf * 8 + c0l + j;
                    if (col < Nrows) s += expf(acc[mf][nf][h * 2 + j] - m);
                }
#pragma unroll
            for (int o = 1; o <= 2; o <<= 1) {
                float m2 = __shfl_xor_sync(0xffffffffu, m, o);
                float s2 = __shfl_xor_sync(0xffffffffu, s, o);
                lse_comb(m, s, m2, s2);
            }
            if ((lane & 3) == 0) {
                int lr = wm * 64 + mf * 16 + h * 8 + r0l;
                partSm[wn * 256 + lr] = make_float2(m, s);
            }
        }
    }
    __syncthreads();
    {
        float2 p0 = partSm[tid];
        float2 p1 = partSm[256 + tid];
        float m = p0.x, s = p0.y;
        lse_comb(m, s, p1.x, p1.y);
        int gi = (mBase + tid) * gridDim.y + blockIdx.y;
        pm[gi] = m;
        ps[gi] = s;
    }
}

// =======================================================================
// attention (per b,h): Qm(16,64) x K(128,64) -> softmax -> x V
// =======================================================================
__global__ __launch_bounds__(128)
void attn_kernel() {
    const int b = blockIdx.x >> 3;
    const int h = blockIdx.x & 7;
    const int tid = threadIdx.x;

    __shared__ float Qs[16][64];
    __shared__ float KVs[128][65];
    __shared__ float Ss[16][128];

    for (int e = tid; e < 16 * 64; e += 128) {
        int q = e >> 6, d = e & 63;
        Qs[q][d] = g_Qm[(b * 16 + q) * D_MODEL + h * DH + d];
    }
    for (int e = tid; e < 128 * 64; e += 128) {
        int s = e >> 6, d = e & 63;
        KVs[s][d] = g_K[(b * S_CURR + s) * D_MODEL + h * DH + d];
    }
    __syncthreads();

    {
        float acc[16];
#pragma unroll
        for (int q = 0; q < 16; q++) acc[q] = 0.f;
#pragma unroll 8
        for (int d = 0; d < 64; d++) {
            float kv = KVs[tid][d];
#pragma unroll
            for (int q = 0; q < 16; q++) acc[q] = fmaf(Qs[q][d], kv, acc[q]);
        }
#pragma unroll
        for (int q = 0; q < 16; q++) Ss[q][tid] = acc[q];
    }
    __syncthreads();

    {
        int w = tid >> 5, lane = tid & 31;
        for (int r = 0; r < 4; r++) {
            int q = w * 4 + r;
            float v[4];
#pragma unroll
            for (int j = 0; j < 4; j++) v[j] = Ss[q][lane + 32 * j];
            float m = fmaxf(fmaxf(v[0], v[1]), fmaxf(v[2], v[3]));
#pragma unroll
            for (int off = 16; off > 0; off >>= 1)
                m = fmaxf(m, __shfl_xor_sync(0xffffffffu, m, off));
            float s = 0.f;
#pragma unroll
            for (int j = 0; j < 4; j++) s += expf(v[j] - m);
#pragma unroll
            for (int off = 16; off > 0; off >>= 1)
                s += __shfl_xor_sync(0xffffffffu, s, off);
            float inv = 1.f / s;
#pragma unroll
            for (int j = 0; j < 4; j++) Ss[q][lane + 32 * j] = expf(v[j] - m) * inv;
        }
    }
    for (int e = tid; e < 128 * 64; e += 128) {
        int s = e >> 6, d = e & 63;
        KVs[s][d] = g_V[(b * S_CURR + s) * D_MODEL + h * DH + d];
    }
    __syncthreads();

    {
        int d = tid & 63;
        int qb = tid >> 6;
#pragma unroll
        for (int qq = 0; qq < 8; qq++) {
            int q = qq * 2 + qb;
            float o = 0.f;
#pragma unroll 8
            for (int t = 0; t < 128; t++) o = fmaf(Ss[q][t], KVs[t][d], o);
            g_att[(b * 16 + q) * D_MODEL + h * DH + d] = o;
        }
    }
}

// =======================================================================
// lse reduce over tiles + subtract
// =======================================================================
__global__ __launch_bounds__(128)
void lse_reduce_kernel() {
    const int row = blockIdx.x;
    const int tid = threadIdx.x;
    float m = -INFINITY, s = 0.f;
    for (int t = tid; t < NT_SCORES; t += 128)
        lse_comb(m, s, g_pm[row * NT_SCORES + t], g_ps[row * NT_SCORES + t]);
    __shared__ float msh[128], ssh[128];
    msh[tid] = m; ssh[tid] = s;
    __syncthreads();
    for (int st = 64; st > 0; st >>= 1) {
        if (tid < st) {
            float mm = msh[tid], ss = ssh[tid];
            lse_comb(mm, ss, msh[tid + st], ssh[tid + st]);
            msh[tid] = mm; ssh[tid] = ss;
        }
        __syncthreads();
    }
    if (tid == 0) g_lse[row] = msh[0] + logf(ssh[0]);
}

__global__ void sub_kernel(float* __restrict__ out) {
    int row = blockIdx.y;
    int i = blockIdx.x * blockDim.x + threadIdx.x;   // float2 index
    if (i >= N_CAND / 2) return;
    float l = g_lse[row];
    float2* p = (float2*)(out + (long long)row * N_CAND) + i;
    float2 v = *p;
    v.x -= l; v.y -= l;
    *p = v;
}

// =======================================================================
// launch
// =======================================================================
extern "C" void kernel_launch(void* const* d_in, const int* in_sizes, int n_in,
                              void* d_out, int out_size) {
    const int*   mask_pos  = (const int*)d_in[2];
    const int*   mask_curr = (const int*)d_in[3];
    const float* emb       = (const float*)d_in[5];
    const float* c_wq      = (const float*)d_in[12];
    const float* c_bq      = (const float*)d_in[13];
    const float* c_wk      = (const float*)d_in[14];
    const float* c_bk      = (const float*)d_in[15];
    const float* c_wv      = (const float*)d_in[16];
    const float* c_bv      = (const float*)d_in[17];
    const float* t2_w      = (const float*)d_in[24];
    const float* t2_b      = (const float*)d_in[25];
    float* out = (float*)d_out;

    __nv_bfloat16 *currhi, *currlo, *qinhi, *qinlo;
    __nv_bfloat16 *wkhi, *wklo, *wvhi, *wvlo, *wqhi, *wqlo, *twhi, *twlo;
    __nv_bfloat16 *embhi, *emblo, *t2ahi, *t2alo, *hybhi, *hyblo;
    float *pK, *pV, *pQm, *pAtt, *pHyb, *pPm, *pPs;
    cudaGetSymbolAddress((void**)&currhi, g_currhi);
    cudaGetSymbolAddress((void**)&currlo, g_currlo);
    cudaGetSymbolAddress((void**)&qinhi,  g_qinhi);
    cudaGetSymbolAddress((void**)&qinlo,  g_qinlo);
    cudaGetSymbolAddress((void**)&wkhi, g_wkhi); cudaGetSymbolAddress((void**)&wklo, g_wklo);
    cudaGetSymbolAddress((void**)&wvhi, g_wvhi); cudaGetSymbolAddress((void**)&wvlo, g_wvlo);
    cudaGetSymbolAddress((void**)&wqhi, g_wqhi); cudaGetSymbolAddress((void**)&wqlo, g_wqlo);
    cudaGetSymbolAddress((void**)&twhi, g_twhi); cudaGetSymbolAddress((void**)&twlo, g_twlo);
    cudaGetSymbolAddress((void**)&embhi, g_embhi);
    cudaGetSymbolAddress((void**)&emblo, g_emblo);
    cudaGetSymbolAddress((void**)&t2ahi, g_t2ahi);
    cudaGetSymbolAddress((void**)&t2alo, g_t2alo);
    cudaGetSymbolAddress((void**)&hybhi, g_hybhi);
    cudaGetSymbolAddress((void**)&hyblo, g_hyblo);
    cudaGetSymbolAddress((void**)&pK,   g_K);
    cudaGetSymbolAddress((void**)&pV,   g_V);
    cudaGetSymbolAddress((void**)&pQm,  g_Qm);
    cudaGetSymbolAddress((void**)&pAtt, g_att);
    cudaGetSymbolAddress((void**)&pHyb, g_hyb);
    cudaGetSymbolAddress((void**)&pPm,  g_pm);
    cudaGetSymbolAddress((void**)&pPs,  g_ps);

    cudaFuncSetAttribute(gemm_bf16_kernel,
                         cudaFuncAttributeMaxDynamicSharedMemorySize, GSMEM);
    cudaFuncSetAttribute(gemm_scores_kernel,
                         cudaFuncAttributeMaxDynamicSharedMemorySize, SSMEM);

    const int W4 = D_MODEL * D_MODEL / 4;   // 65536

    // 0) pre-split static operands
    split_kernel<<<(N_CAND * 128 + 255) / 256, 256>>>(emb + 2 * D_MODEL, embhi, emblo,
                                                      N_CAND * 128);
    split4w_kernel<<<(4 * W4) / 256, 256>>>(c_wk, c_wv, c_wq, t2_w,
                                            wkhi, wklo, wvhi, wvlo,
                                            wqhi, wqlo, twhi, twlo);

    // 1) embeddings + positional encodings (direct hi/lo)
    build_curr_kernel<<<(NROWS_KV * D_MODEL / 4) / 256, 256>>>(mask_curr, emb);
    build_qin_kernel<<<(M_GATH * D_MODEL / 4) / 256, 256>>>(mask_curr, mask_pos, emb);

    // 2) projections
    gemm_bf16_kernel<<<dim3(32, 4), 512, GSMEM>>>(currhi, currlo, wkhi, wklo,
                                                  c_bk, pK, D_MODEL, D_MODEL);
    gemm_bf16_kernel<<<dim3(32, 4), 512, GSMEM>>>(currhi, currlo, wvhi, wvlo,
                                                  c_bv, pV, D_MODEL, D_MODEL);
    gemm_bf16_kernel<<<dim3(4, 4), 512, GSMEM>>>(qinhi, qinlo, wqhi, wqlo,
                                                 c_bq, pQm, D_MODEL, D_MODEL);

    // 3) attention
    attn_kernel<<<BATCH * HEADS, 128>>>();

    // 4) hyb = tanh(att) @ t2_w^T + t2_b
    tanh_split_kernel<<<W4 / 256, 256>>>(pAtt, t2ahi, t2alo, W4);
    gemm_bf16_kernel<<<dim3(4, 4), 512, GSMEM>>>(t2ahi, t2alo, twhi, twlo,
                                                 t2_b, pHyb, D_MODEL, D_MODEL);
    split_kernel<<<W4 / 256, 256>>>(pHyb, hybhi, hyblo, W4);

    // 5) scores + fused partial logsumexp (256x128 tiles, 64x64 warp tiles)
    gemm_scores_kernel<<<dim3(2, NT_SCORES), 256, SSMEM>>>(
        hybhi, hyblo, embhi, emblo, out, N_CAND, N_CAND, pPm, pPs);

    // 6) finish log_softmax
    lse_reduce_kernel<<<M_GATH, 128>>>();
    {
        dim3 grid((N_CAND / 2 + 255) / 256, M_GATH);
        sub_kernel<<<grid, 256>>>(out);
    }
}

// round 17
// speedup vs baseline: 1.4551x; 1.4551x over previous
#include <cuda_runtime.h>
#include <cuda_bf16.h>
#include <cuda_fp16.h>
#include <math.h>
#include <stdint.h>

// ---------------- problem constants ----------------
#define D_MODEL   512
#define HEADS     8
#define DH        64
#define BATCH     32
#define S_CURR    128
#define N_MASK    16
#define N_CAND    39998
#define M_GATH    (BATCH * N_MASK)   // 512
#define NROWS_KV  (BATCH * S_CURR)   // 4096

// ---------------- scratch (static device memory) ----------------
__device__ __nv_bfloat16 g_currhi[NROWS_KV * D_MODEL];
__device__ __nv_bfloat16 g_currlo[NROWS_KV * D_MODEL];
__device__ __nv_bfloat16 g_qinhi [M_GATH * D_MODEL];
__device__ __nv_bfloat16 g_qinlo [M_GATH * D_MODEL];
__device__ __nv_bfloat16 g_wkhi[D_MODEL * D_MODEL], g_wklo[D_MODEL * D_MODEL];
__device__ __nv_bfloat16 g_wvhi[D_MODEL * D_MODEL], g_wvlo[D_MODEL * D_MODEL];
__device__ __nv_bfloat16 g_wqhi[D_MODEL * D_MODEL], g_wqlo[D_MODEL * D_MODEL];
__device__ __nv_bfloat16 g_twhi[D_MODEL * D_MODEL], g_twlo[D_MODEL * D_MODEL];
__device__ __half g_embh[(size_t)N_CAND * D_MODEL];      // fp16 candidates
__device__ __half g_hybh[M_GATH * D_MODEL];              // fp16 hyb
__device__ __nv_bfloat16 g_t2ahi[M_GATH * D_MODEL], g_t2alo[M_GATH * D_MODEL];
__device__ float g_K  [NROWS_KV * D_MODEL];
__device__ float g_V  [NROWS_KV * D_MODEL];
__device__ float g_Qm [M_GATH * D_MODEL];
__device__ float g_att[M_GATH * D_MODEL];
__device__ float g_hyb[M_GATH * D_MODEL];
#define NT_SCORES 313                 // ceil(40064/128)
__device__ float g_pm[M_GATH * NT_SCORES];
__device__ float g_ps[M_GATH * NT_SCORES];
__device__ float g_lse[M_GATH];

// =======================================================================
// helpers
// =======================================================================
__device__ __forceinline__ uint32_t smem_u32(const void* p) {
    uint32_t a;
    asm("{ .reg .u64 t; cvta.to.shared.u64 t, %1; cvt.u32.u64 %0, t; }"
        : "=r"(a) : "l"(p));
    return a;
}

#define LDSM4(r0, r1, r2, r3, addr) \
    asm volatile("ldmatrix.sync.aligned.m8n8.x4.shared.b16 {%0,%1,%2,%3}, [%4];" \
                 : "=r"(r0), "=r"(r1), "=r"(r2), "=r"(r3) : "r"(addr))

#define MMA16816(d, a, b) \
    asm volatile("mma.sync.aligned.m16n8k16.row.col.f32.bf16.bf16.f32 " \
                 "{%0,%1,%2,%3}, {%4,%5,%6,%7}, {%8,%9}, {%0,%1,%2,%3};" \
                 : "+f"((d)[0]), "+f"((d)[1]), "+f"((d)[2]), "+f"((d)[3]) \
                 : "r"((a)[0]), "r"((a)[1]), "r"((a)[2]), "r"((a)[3]), \
                   "r"((b)[0]), "r"((b)[1]))

#define MMA16816H(d, a, b) \
    asm volatile("mma.sync.aligned.m16n8k16.row.col.f32.f16.f16.f32 " \
                 "{%0,%1,%2,%3}, {%4,%5,%6,%7}, {%8,%9}, {%0,%1,%2,%3};" \
                 : "+f"((d)[0]), "+f"((d)[1]), "+f"((d)[2]), "+f"((d)[3]) \
                 : "r"((a)[0]), "r"((a)[1]), "r"((a)[2]), "r"((a)[3]), \
                   "r"((b)[0]), "r"((b)[1]))

#define CP_ASYNC16(dst, src, sz) \
    asm volatile("cp.async.cg.shared.global [%0], [%1], 16, %2;" \
                 :: "r"(dst), "l"(src), "r"(sz))
#define CP_COMMIT() asm volatile("cp.async.commit_group;" ::: "memory")
#define CP_WAIT2()  asm volatile("cp.async.wait_group 2;" ::: "memory")

// safe logsumexp combine
__device__ __forceinline__ void lse_comb(float& m, float& s, float m2, float s2) {
    float M = fmaxf(m, m2);
    if (M == -INFINITY) { m = M; s = 0.f; return; }
    s = s * expf(m - M) + s2 * expf(m2 - M);
    m = M;
}

// split one float4 into packed bf16 hi/lo
__device__ __forceinline__ void split4(float4 v, uint2& h, uint2& l) {
    __nv_bfloat162 h01 = __floats2bfloat162_rn(v.x, v.y);
    __nv_bfloat162 h23 = __floats2bfloat162_rn(v.z, v.w);
    float lx = v.x - __bfloat162float(h01.x);
    float ly = v.y - __bfloat162float(h01.y);
    float lz = v.z - __bfloat162float(h23.x);
    float lw = v.w - __bfloat162float(h23.y);
    __nv_bfloat162 l01 = __floats2bfloat162_rn(lx, ly);
    __nv_bfloat162 l23 = __floats2bfloat162_rn(lz, lw);
    h = make_uint2(*reinterpret_cast<unsigned*>(&h01), *reinterpret_cast<unsigned*>(&h23));
    l = make_uint2(*reinterpret_cast<unsigned*>(&l01), *reinterpret_cast<unsigned*>(&l23));
}

// =======================================================================
// conversion kernels
// =======================================================================
__global__ void convh_kernel(const float* __restrict__ src,
                             __half* __restrict__ dst, int n4) {
    int i = blockIdx.x * blockDim.x + threadIdx.x;
    if (i >= n4) return;
    float4 v = ((const float4*)src)[i];
    __half2 h01 = __floats2half2_rn(v.x, v.y);
    __half2 h23 = __floats2half2_rn(v.z, v.w);
    ((uint2*)dst)[i] = make_uint2(*reinterpret_cast<unsigned*>(&h01),
                                  *reinterpret_cast<unsigned*>(&h23));
}

// fused split of the four 512x512 weight matrices (one launch)
__global__ void split4w_kernel(const float* __restrict__ w0, const float* __restrict__ w1,
                               const float* __restrict__ w2, const float* __restrict__ w3,
                               __nv_bfloat16* __restrict__ h0, __nv_bfloat16* __restrict__ l0,
                               __nv_bfloat16* __restrict__ h1, __nv_bfloat16* __restrict__ l1,
                               __nv_bfloat16* __restrict__ h2, __nv_bfloat16* __restrict__ l2,
                               __nv_bfloat16* __restrict__ h3, __nv_bfloat16* __restrict__ l3) {
    const int W4 = D_MODEL * D_MODEL / 4;
    int i = blockIdx.x * blockDim.x + threadIdx.x;
    int which = i / W4;
    int j = i - which * W4;
    const float* src; __nv_bfloat16 *hi, *lo;
    if      (which == 0) { src = w0; hi = h0; lo = l0; }
    else if (which == 1) { src = w1; hi = h1; lo = l1; }
    else if (which == 2) { src = w2; hi = h2; lo = l2; }
    else                 { src = w3; hi = h3; lo = l3; }
    uint2 h, l;
    split4(((const float4*)src)[j], h, l);
    ((uint2*)hi)[j] = h;
    ((uint2*)lo)[j] = l;
}

__global__ void tanh_split_kernel(const float* __restrict__ src,
                                  __nv_bfloat16* __restrict__ hi,
                                  __nv_bfloat16* __restrict__ lo, int n4) {
    int i = blockIdx.x * blockDim.x + threadIdx.x;
    if (i >= n4) return;
    float4 v = ((const float4*)src)[i];
    v.x = tanhf(v.x); v.y = tanhf(v.y); v.z = tanhf(v.z); v.w = tanhf(v.w);
    uint2 h, l;
    split4(v, h, l);
    ((uint2*)hi)[i] = h;
    ((uint2*)lo)[i] = l;
}

// =======================================================================
// positional embedding + gathers (write bf16 hi/lo directly)
// =======================================================================
__device__ __forceinline__ float pe_val(int pos, int d) {
    const float c = -9.210340371976184f / (float)D_MODEL;  // -ln(10000)/512
    int i2 = d & ~1;
    float freq = expf((float)i2 * c);
    float arg = (float)pos * freq;
    return (d & 1) ? cosf(arg) : sinf(arg);
}

__global__ void build_curr_kernel(const int* __restrict__ idx,
                                  const float* __restrict__ emb) {
    int t = blockIdx.x * blockDim.x + threadIdx.x;     // one float4
    if (t >= NROWS_KV * D_MODEL / 4) return;
    int e  = t * 4;
    int d0 = e & (D_MODEL - 1);
    int row = e >> 9;
    int s  = row & (S_CURR - 1);
    int g  = idx[row];
    float4 v = *(const float4*)(emb + (size_t)g * D_MODEL + d0);
    v.x += pe_val(s, d0);     v.y += pe_val(s, d0 + 1);
    v.z += pe_val(s, d0 + 2); v.w += pe_val(s, d0 + 3);
    uint2 h, l;
    split4(v, h, l);
    ((uint2*)g_currhi)[t] = h;
    ((uint2*)g_currlo)[t] = l;
}

__global__ void build_qin_kernel(const int* __restrict__ idx,
                                 const int* __restrict__ mask_pos,
                                 const float* __restrict__ emb) {
    int t = blockIdx.x * blockDim.x + threadIdx.x;
    if (t >= M_GATH * D_MODEL / 4) return;
    int e  = t * 4;
    int d0 = e & (D_MODEL - 1);
    int r  = e >> 9;                  // b*16+i
    int b  = r >> 4;
    int s  = mask_pos[r];
    int g  = idx[b * S_CURR + s];
    float4 v = *(const float4*)(emb + (size_t)g * D_MODEL + d0);
    v.x += pe_val(s, d0);     v.y += pe_val(s, d0 + 1);
    v.z += pe_val(s, d0 + 2); v.w += pe_val(s, d0 + 3);
    uint2 h, l;
    split4(v, h, l);
    ((uint2*)g_qinhi)[t] = h;
    ((uint2*)g_qinlo)[t] = l;
}

// =======================================================================
// projections GEMM (3-pass bf16 hi/lo, CTA 128x128, 512 threads, 16 warps
// 4x4, warp tile 32x32, 4-stage cp.async) — unchanged from round 15
// =======================================================================
#define NCHUNK   16
#define LDTB     80
#define TILE_SZ  (128 * LDTB)        // 10240
#define OFF_AHI  0u
#define OFF_ALO  (1u * TILE_SZ)
#define OFF_BHI  (2u * TILE_SZ)
#define OFF_BLO  (3u * TILE_SZ)
#define STAGE_SZ (4u * TILE_SZ)      // 40960
#define GSMEM    (4 * 40960)         // 163840

__device__ __forceinline__ void issue_chunk(
    uint32_t stBase,
    const __nv_bfloat16* __restrict__ Ahi, const __nv_bfloat16* __restrict__ Alo,
    const __nv_bfloat16* __restrict__ Bhi, const __nv_bfloat16* __restrict__ Blo,
    int mBase, int nBase, int Nrows, int kt, int tid)
{
#pragma unroll
    for (int i = 0; i < 4; i++) {
        int idx  = tid + i * 512;     // 0..2047
        int tile = idx >> 9;
        int w    = idx & 511;
        int row  = w >> 2;
        int c16  = w & 3;
        uint32_t dst = stBase + tile * TILE_SZ + row * LDTB + c16 * 16;
        const __nv_bfloat16* base =
            (tile == 0) ? Ahi : (tile == 1) ? Alo : (tile == 2) ? Bhi : Blo;
        int gr = (tile < 2) ? (mBase + row) : (nBase + row);
        int sz = 16;
        if (tile >= 2 && gr >= Nrows) { sz = 0; gr = 0; }
        const char* src = (const char*)base + (long long)gr * 1024 + kt * 64 + c16 * 16;
        CP_ASYNC16(dst, src, sz);
    }
}

#define LOADF(s, buf) do {                                                   \
    uint32_t aT = smb + sOff + AO[s] + mW * LDTB + laneOff + KO[s];          \
    LDSM4(a2[buf][0][0], a2[buf][0][1], a2[buf][0][2], a2[buf][0][3], aT);   \
    LDSM4(a2[buf][1][0], a2[buf][1][1], a2[buf][1][2], a2[buf][1][3],       \
          aT + 16 * LDTB);                                                   \
    uint32_t bT = smb + sOff + BO[s] + nW * LDTB + laneOff + KO[s];          \
    uint32_t r0_, r1_, r2_, r3_;                                             \
    LDSM4(r0_, r1_, r2_, r3_, bT);                                           \
    b2[buf][0][0] = r0_; b2[buf][0][1] = r2_;                                \
    b2[buf][1][0] = r1_; b2[buf][1][1] = r3_;                                \
    LDSM4(r0_, r1_, r2_, r3_, bT + 16 * LDTB);                               \
    b2[buf][2][0] = r0_; b2[buf][2][1] = r2_;                                \
    b2[buf][3][0] = r1_; b2[buf][3][1] = r3_;                                \
} while (0)

__global__ __launch_bounds__(512, 1)
void gemm_bf16_kernel(const __nv_bfloat16* __restrict__ Ahi,
                      const __nv_bfloat16* __restrict__ Alo,
                      const __nv_bfloat16* __restrict__ Bhi,
                      const __nv_bfloat16* __restrict__ Blo,
                      const float* __restrict__ bias,
                      float* __restrict__ C,
                      int Nrows, int ldc)
{
    extern __shared__ char sm[];
    const uint32_t smb = smem_u32(sm);
    const int tid  = threadIdx.x;
    const int lane = tid & 31;
    const int wid  = tid >> 5;
    const int mBase = blockIdx.x * 128;
    const int nBase = blockIdx.y * 128;
    const int mW = (wid & 3) * 32;
    const int nW = (wid >> 2) * 32;
    const uint32_t laneOff = (lane & 15) * LDTB + (lane >> 4) * 16;

    float acc[2][4][4];
#pragma unroll
    for (int mf = 0; mf < 2; mf++)
#pragma unroll
        for (int nf = 0; nf < 4; nf++)
#pragma unroll
            for (int j = 0; j < 4; j++) acc[mf][nf][j] = 0.f;

#pragma unroll
    for (int c = 0; c < 3; c++) {
        issue_chunk(smb + c * STAGE_SZ, Ahi, Alo, Bhi, Blo,
                    mBase, nBase, Nrows, c, tid);
        CP_COMMIT();
    }

    const uint32_t AO[6] = {OFF_AHI, OFF_AHI, OFF_AHI, OFF_AHI, OFF_ALO, OFF_ALO};
    const uint32_t BO[6] = {OFF_BHI, OFF_BHI, OFF_BLO, OFF_BLO, OFF_BHI, OFF_BHI};
    const uint32_t KO[6] = {0, 32, 0, 32, 0, 32};

#pragma unroll 1
    for (int kt = 0; kt < NCHUNK; kt++) {
        CP_WAIT2();
        __syncthreads();
        if (kt + 3 < NCHUNK)
            issue_chunk(smb + ((kt + 3) & 3) * STAGE_SZ, Ahi, Alo, Bhi, Blo,
                        mBase, nBase, Nrows, kt + 3, tid);
        CP_COMMIT();

        const uint32_t sOff = (kt & 3) * STAGE_SZ;
        uint32_t a2[2][2][4];
        uint32_t b2[2][4][2];
        LOADF(0, 0);
#pragma unroll
        for (int s = 0; s < 6; s++) {
            const int cur = s & 1;
            if (s < 5) LOADF(s + 1, cur ^ 1);
#pragma unroll
            for (int mf = 0; mf < 2; mf++)
#pragma unroll
                for (int nf = 0; nf < 4; nf++)
                    MMA16816(acc[mf][nf], a2[cur][mf], b2[cur][nf]);
        }
    }

    const int r0l = lane >> 2;
    const int c0l = (lane & 3) * 2;
#pragma unroll
    for (int mf = 0; mf < 2; mf++) {
#pragma unroll
        for (int nf = 0; nf < 4; nf++) {
            int row = mBase + mW + mf * 16 + r0l;
            int col = nBase + nW + nf * 8 + c0l;
            float* cp0 = C + (long long)row * ldc;
            float* cp1 = C + (long long)(row + 8) * ldc;
            if (col + 1 < Nrows) {
                float b0 = bias ? bias[col] : 0.f;
                float b1 = bias ? bias[col + 1] : 0.f;
                *(float2*)(cp0 + col) = make_float2(acc[mf][nf][0] + b0,
                                                    acc[mf][nf][1] + b1);
                *(float2*)(cp1 + col) = make_float2(acc[mf][nf][2] + b0,
                                                    acc[mf][nf][3] + b1);
            } else if (col < Nrows) {
                float b0 = bias ? bias[col] : 0.f;
                cp0[col] = acc[mf][nf][0] + b0;
                cp1[col] = acc[mf][nf][2] + b0;
            }
        }
    }
}

// =======================================================================
// scores GEMM: SINGLE-PASS fp16. CTA tile 256x128, 256 threads, 8 warps
// 4x2, warp tile 64x64. K-chunk 64 (8 chunks), 3-stage cp.async.
// Fused per-tile logsumexp partials.
// =======================================================================
#define SC_NCH   8
#define SC_LDTB  144                 // 128 B data + 16 pad
#define SC_AOFF  0u
#define SC_BOFF  36864u              // 256*144
#define SC_STAGE 55296u              // + 128*144
#define SC_SMEM  (3 * 55296)         // 165888

__device__ __forceinline__ void issue_chunk_h(
    uint32_t stBase,
    const __half* __restrict__ A, const __half* __restrict__ B,
    int mBase, int nBase, int Nrows, int kt, int tid)
{
    // A: 256 rows x 8 16B segs = 2048 ops
#pragma unroll
    for (int i = 0; i < 8; i++) {
        int idx = tid + i * 256;
        int row = idx >> 3, c16 = idx & 7;
        uint32_t dst = stBase + SC_AOFF + row * SC_LDTB + c16 * 16;
        const char* src = (const char*)A + (long long)(mBase + row) * 1024
                          + kt * 128 + c16 * 16;
        CP_ASYNC16(dst, src, 16);
    }
    // B: 128 rows x 8 = 1024 ops
#pragma unroll
    for (int i = 0; i < 4; i++) {
        int idx = tid + i * 256;
        int row = idx >> 3, c16 = idx & 7;
        int gr = nBase + row;
        int sz = (gr < Nrows) ? 16 : 0;
        if (!sz) gr = 0;
        uint32_t dst = stBase + SC_BOFF + row * SC_LDTB + c16 * 16;
        const char* src = (const char*)B + (long long)gr * 1024
                          + kt * 128 + c16 * 16;
        CP_ASYNC16(dst, src, sz);
    }
}

__global__ __launch_bounds__(256, 1)
void gemm_scores_h_kernel(const __half* __restrict__ A,
                          const __half* __restrict__ B,
                          float* __restrict__ C,
                          int Nrows, int ldc,
                          float* __restrict__ pm, float* __restrict__ ps)
{
    extern __shared__ char sm[];
    const uint32_t smb = smem_u32(sm);
    const int tid  = threadIdx.x;
    const int lane = tid & 31;
    const int wid  = tid >> 5;
    const int mBase = blockIdx.x * 256;
    const int nBase = blockIdx.y * 128;
    const int mW = (wid & 3) * 64;      // 4 warps in m
    const int nW = (wid >> 2) * 64;     // 2 warps in n
    const uint32_t laneOff = (lane & 15) * SC_LDTB + (lane >> 4) * 16;

    float acc[4][8][4];
#pragma unroll
    for (int mf = 0; mf < 4; mf++)
#pragma unroll
        for (int nf = 0; nf < 8; nf++)
#pragma unroll
            for (int j = 0; j < 4; j++) acc[mf][nf][j] = 0.f;

#pragma unroll
    for (int c = 0; c < 3; c++) {
        issue_chunk_h(smb + c * SC_STAGE, A, B, mBase, nBase, Nrows, c, tid);
        CP_COMMIT();
    }

    int stage = 0;
#pragma unroll 1
    for (int kt = 0; kt < SC_NCH; kt++) {
        CP_WAIT2();
        __syncthreads();
        const uint32_t sOff = stage * SC_STAGE;
#pragma unroll
        for (int s = 0; s < 4; s++) {          // 4 k16 steps (K-chunk 64)
            uint32_t a[4][4];
            uint32_t b[8][2];
            uint32_t aT = smb + sOff + SC_AOFF + mW * SC_LDTB + laneOff + s * 32;
#pragma unroll
            for (int q = 0; q < 4; q++)
                LDSM4(a[q][0], a[q][1], a[q][2], a[q][3], aT + q * 16 * SC_LDTB);
            uint32_t bT = smb + sOff + SC_BOFF + nW * SC_LDTB + laneOff + s * 32;
#pragma unroll
            for (int q = 0; q < 4; q++) {
                uint32_t r0, r1, r2, r3;
                LDSM4(r0, r1, r2, r3, bT + q * 16 * SC_LDTB);
                b[2 * q][0] = r0;      b[2 * q][1] = r2;
                b[2 * q + 1][0] = r1;  b[2 * q + 1][1] = r3;
            }
#pragma unroll
            for (int mf = 0; mf < 4; mf++)
#pragma unroll
                for (int nf = 0; nf < 8; nf++)
                    MMA16816H(acc[mf][nf], a[mf], b[nf]);
        }
        if (kt + 3 < SC_NCH) {
            __syncthreads();          // all warps done reading this stage
            issue_chunk_h(smb + stage * SC_STAGE, A, B, mBase, nBase, Nrows,
                          kt + 3, tid);
        }
        CP_COMMIT();                  // empty groups keep wait accounting uniform
        stage = (stage == 2) ? 0 : stage + 1;
    }

    // ---------------- C write ----------------
    const int r0l = lane >> 2;
    const int c0l = (lane & 3) * 2;
#pragma unroll
    for (int mf = 0; mf < 4; mf++) {
#pragma unroll
        for (int nf = 0; nf < 8; nf++) {
            int row = mBase + mW + mf * 16 + r0l;
            int col = nBase + nW + nf * 8 + c0l;
            float* cp0 = C + (long long)row * ldc;
            float* cp1 = C + (long long)(row + 8) * ldc;
            if (col + 1 < Nrows) {
                *(float2*)(cp0 + col) = make_float2(acc[mf][nf][0], acc[mf][nf][1]);
                *(float2*)(cp1 + col) = make_float2(acc[mf][nf][2], acc[mf][nf][3]);
            } else if (col < Nrows) {
                cp0[col] = acc[mf][nf][0];
                cp1[col] = acc[mf][nf][2];
            }
        }
    }

    // ---------------- fused logsumexp partials ----------------
    __syncthreads();                    // stage smem free for reuse
    float2* partSm = (float2*)sm;       // 2 x 256 float2 = 4 KB
    const int wm = wid & 3;
    const int wn = wid >> 2;
#pragma unroll
    for (int mf = 0; mf < 4; mf++) {
#pragma unroll
        for (int h = 0; h < 2; h++) {
            float m = -INFINITY;
#pragma unroll
            for (int nf = 0; nf < 8; nf++)
#pragma unroll
                for (int j = 0; j < 2; j++) {
                    int col = nBase + nW + nf * 8 + c0l + j;
                    if (col < Nrows) m = fmaxf(m, acc[mf][nf][h * 2 + j]);
                }
            float s = 0.f;
#pragma unroll
            for (int nf = 0; nf < 8; nf++)
#pragma unroll
                for (int j = 0; j < 2; j++) {
                    int col = nBase + nW + nf * 8 + c0l + j;
                    if (col < Nrows) s += expf(acc[mf][nf][h * 2 + j] - m);
                }
#pragma unroll
            for (int o = 1; o <= 2; o <<= 1) {
                float m2 = __shfl_xor_sync(0xffffffffu, m, o);
                float s2 = __shfl_xor_sync(0xffffffffu, s, o);
                lse_comb(m, s, m2, s2);
            }
            if ((lane & 3) == 0) {
                int lr = wm * 64 + mf * 16 + h * 8 + r0l;
                partSm[wn * 256 + lr] = make_float2(m, s);
            }
        }
    }
    __syncthreads();
    {
        float2 p0 = partSm[tid];
        float2 p1 = partSm[256 + tid];
        float m = p0.x, s = p0.y;
        lse_comb(m, s, p1.x, p1.y);
        int gi = (mBase + tid) * gridDim.y + blockIdx.y;
        pm[gi] = m;
        ps[gi] = s;
    }
}

// =======================================================================
// attention (per b,h): Qm(16,64) x K(128,64) -> softmax -> x V
// =======================================================================
__global__ __launch_bounds__(128)
void attn_kernel() {
    const int b = blockIdx.x >> 3;
    const int h = blockIdx.x & 7;
    const int tid = threadIdx.x;

    __shared__ float Qs[16][64];
    __shared__ float KVs[128][65];
    __shared__ float Ss[16][128];

    for (int e = tid; e < 16 * 64; e += 128) {
        int q = e >> 6, d = e & 63;
        Qs[q][d] = g_Qm[(b * 16 + q) * D_MODEL + h * DH + d];
    }
    for (int e = tid; e < 128 * 64; e += 128) {
        int s = e >> 6, d = e & 63;
        KVs[s][d] = g_K[(b * S_CURR + s) * D_MODEL + h * DH + d];
    }
    __syncthreads();

    {
        float acc[16];
#pragma unroll
        for (int q = 0; q < 16; q++) acc[q] = 0.f;
#pragma unroll 8
        for (int d = 0; d < 64; d++) {
            float kv = KVs[tid][d];
#pragma unroll
            for (int q = 0; q < 16; q++) acc[q] = fmaf(Qs[q][d], kv, acc[q]);
        }
#pragma unroll
        for (int q = 0; q < 16; q++) Ss[q][tid] = acc[q];
    }
    __syncthreads();

    {
        int w = tid >> 5, lane = tid & 31;
        for (int r = 0; r < 4; r++) {
            int q = w * 4 + r;
            float v[4];
#pragma unroll
            for (int j = 0; j < 4; j++) v[j] = Ss[q][lane + 32 * j];
            float m = fmaxf(fmaxf(v[0], v[1]), fmaxf(v[2], v[3]));
#pragma unroll
            for (int off = 16; off > 0; off >>= 1)
                m = fmaxf(m, __shfl_xor_sync(0xffffffffu, m, off));
            float s = 0.f;
#pragma unroll
            for (int j = 0; j < 4; j++) s += expf(v[j] - m);
#pragma unroll
            for (int off = 16; off > 0; off >>= 1)
                s += __shfl_xor_sync(0xffffffffu, s, off);
            float inv = 1.f / s;
#pragma unroll
            for (int j = 0; j < 4; j++) Ss[q][lane + 32 * j] = expf(v[j] - m) * inv;
        }
    }
    for (int e = tid; e < 128 * 64; e += 128) {
        int s = e >> 6, d = e & 63;
        KVs[s][d] = g_V[(b * S_CURR + s) * D_MODEL + h * DH + d];
    }
    __syncthreads();

    {
        int d = tid & 63;
        int qb = tid >> 6;
#pragma unroll
        for (int qq = 0; qq < 8; qq++) {
            int q = qq * 2 + qb;
            float o = 0.f;
#pragma unroll 8
            for (int t = 0; t < 128; t++) o = fmaf(Ss[q][t], KVs[t][d], o);
            g_att[(b * 16 + q) * D_MODEL + h * DH + d] = o;
        }
    }
}

// =======================================================================
// lse reduce over tiles + subtract
// =======================================================================
__global__ __launch_bounds__(128)
void lse_reduce_kernel() {
    const int row = blockIdx.x;
    const int tid = threadIdx.x;
    float m = -INFINITY, s = 0.f;
    for (int t = tid; t < NT_SCORES; t += 128)
        lse_comb(m, s, g_pm[row * NT_SCORES + t], g_ps[row * NT_SCORES + t]);
    __shared__ float msh[128], ssh[128];
    msh[tid] = m; ssh[tid] = s;
    __syncthreads();
    for (int st = 64; st > 0; st >>= 1) {
        if (tid < st) {
            float mm = msh[tid], ss = ssh[tid];
            lse_comb(mm, ss, msh[tid + st], ssh[tid + st]);
            msh[tid] = mm; ssh[tid] = ss;
        }
        __syncthreads();
    }
    if (tid == 0) g_lse[row] = msh[0] + logf(ssh[0]);
}

__global__ void sub_kernel(float* __restrict__ out) {
    int row = blockIdx.y;
    int i = blockIdx.x * blockDim.x + threadIdx.x;   // float2 index
    if (i >= N_CAND / 2) return;
    float l = g_lse[row];
    float2* p = (float2*)(out + (long long)row * N_CAND) + i;
    float2 v = *p;
    v.x -= l; v.y -= l;
    *p = v;
}

// =======================================================================
// launch
// =======================================================================
extern "C" void kernel_launch(void* const* d_in, const int* in_sizes, int n_in,
                              void* d_out, int out_size) {
    const int*   mask_pos  = (const int*)d_in[2];
    const int*   mask_curr = (const int*)d_in[3];
    const float* emb       = (const float*)d_in[5];
    const float* c_wq      = (const float*)d_in[12];
    const float* c_bq      = (const float*)d_in[13];
    const float* c_wk      = (const float*)d_in[14];
    const float* c_bk      = (const float*)d_in[15];
    const float* c_wv      = (const float*)d_in[16];
    const float* c_bv      = (const float*)d_in[17];
    const float* t2_w      = (const float*)d_in[24];
    const float* t2_b      = (const float*)d_in[25];
    float* out = (float*)d_out;

    __nv_bfloat16 *currhi, *currlo, *qinhi, *qinlo;
    __nv_bfloat16 *wkhi, *wklo, *wvhi, *wvlo, *wqhi, *wqlo, *twhi, *twlo;
    __nv_bfloat16 *t2ahi, *t2alo;
    __half *embh, *hybh;
    float *pK, *pV, *pQm, *pAtt, *pHyb, *pPm, *pPs;
    cudaGetSymbolAddress((void**)&currhi, g_currhi);
    cudaGetSymbolAddress((void**)&currlo, g_currlo);
    cudaGetSymbolAddress((void**)&qinhi,  g_qinhi);
    cudaGetSymbolAddress((void**)&qinlo,  g_qinlo);
    cudaGetSymbolAddress((void**)&wkhi, g_wkhi); cudaGetSymbolAddress((void**)&wklo, g_wklo);
    cudaGetSymbolAddress((void**)&wvhi, g_wvhi); cudaGetSymbolAddress((void**)&wvlo, g_wvlo);
    cudaGetSymbolAddress((void**)&wqhi, g_wqhi); cudaGetSymbolAddress((void**)&wqlo, g_wqlo);
    cudaGetSymbolAddress((void**)&twhi, g_twhi); cudaGetSymbolAddress((void**)&twlo, g_twlo);
    cudaGetSymbolAddress((void**)&embh, g_embh);
    cudaGetSymbolAddress((void**)&hybh, g_hybh);
    cudaGetSymbolAddress((void**)&t2ahi, g_t2ahi);
    cudaGetSymbolAddress((void**)&t2alo, g_t2alo);
    cudaGetSymbolAddress((void**)&pK,   g_K);
    cudaGetSymbolAddress((void**)&pV,   g_V);
    cudaGetSymbolAddress((void**)&pQm,  g_Qm);
    cudaGetSymbolAddress((void**)&pAtt, g_att);
    cudaGetSymbolAddress((void**)&pHyb, g_hyb);
    cudaGetSymbolAddress((void**)&pPm,  g_pm);
    cudaGetSymbolAddress((void**)&pPs,  g_ps);

    cudaFuncSetAttribute(gemm_bf16_kernel,
                         cudaFuncAttributeMaxDynamicSharedMemorySize, GSMEM);
    cudaFuncSetAttribute(gemm_scores_h_kernel,
                         cudaFuncAttributeMaxDynamicSharedMemorySize, SC_SMEM);

    const int W4 = D_MODEL * D_MODEL / 4;   // 65536

    // 0) pre-convert static operands
    convh_kernel<<<(N_CAND * 128 + 255) / 256, 256>>>(emb + 2 * D_MODEL, embh,
                                                      N_CAND * 128);
    split4w_kernel<<<(4 * W4) / 256, 256>>>(c_wk, c_wv, c_wq, t2_w,
                                            wkhi, wklo, wvhi, wvlo,
                                            wqhi, wqlo, twhi, twlo);

    // 1) embeddings + positional encodings (direct hi/lo)
    build_curr_kernel<<<(NROWS_KV * D_MODEL / 4) / 256, 256>>>(mask_curr, emb);
    build_qin_kernel<<<(M_GATH * D_MODEL / 4) / 256, 256>>>(mask_curr, mask_pos, emb);

    // 2) projections (3-pass bf16 — precision-critical path)
    gemm_bf16_kernel<<<dim3(32, 4), 512, GSMEM>>>(currhi, currlo, wkhi, wklo,
                                                  c_bk, pK, D_MODEL, D_MODEL);
    gemm_bf16_kernel<<<dim3(32, 4), 512, GSMEM>>>(currhi, currlo, wvhi, wvlo,
                                                  c_bv, pV, D_MODEL, D_MODEL);
    gemm_bf16_kernel<<<dim3(4, 4), 512, GSMEM>>>(qinhi, qinlo, wqhi, wqlo,
                                                 c_bq, pQm, D_MODEL, D_MODEL);

    // 3) attention
    attn_kernel<<<BATCH * HEADS, 128>>>();

    // 4) hyb = tanh(att) @ t2_w^T + t2_b  (3-pass bf16), then fp16 convert
    tanh_split_kernel<<<W4 / 256, 256>>>(pAtt, t2ahi, t2alo, W4);
    gemm_bf16_kernel<<<dim3(4, 4), 512, GSMEM>>>(t2ahi, t2alo, twhi, twlo,
                                                 t2_b, pHyb, D_MODEL, D_MODEL);
    convh_kernel<<<W4 / 256, 256>>>(pHyb, hybh, W4);

    // 5) scores = hyb @ emb[2:]^T — single-pass fp16 + fused lse partials
    gemm_scores_h_kernel<<<dim3(2, NT_SCORES), 256, SC_SMEM>>>(
        hybh, embh, out, N_CAND, N_CAND, pPm, pPs);

    // 6) finish log_softmax
    lse_reduce_kernel<<<M_GATH, 128>>>();
    {
        dim3 grid((N_CAND / 2 + 255) / 256, M_GATH);
        sub_kernel<<<grid, 256>>>(out);
    }
}